// round 13
// baseline (speedup 1.0000x reference)
#include <cuda_runtime.h>

// x: (B=16, C=512, H=62, W=62) fp32, row-major.
// 9 regions: 2x2 patches at (y,x), y,x in {0,30,60}. flat base = y*62 + x.
// Patch elements: base, base+1, base+62, base+63. Pairs: (2k, 2k+1).
#define HW      3844
#define WIDTH   62
#define CHN     512
#define NPAIR   8
#define NREG    9
#define NCHUNK  16
#define NBLK    (NCHUNK * NPAIR)   // 128
#define NCELL   (NPAIR * NREG)     // 72
#define EPSV    1e-6f
#define FXSCALE 268435456.0        // 2^28: exact double product with fp32 inputs

__constant__ int c_posbase[9] = {0, 30, 60, 1860, 1890, 1920, 3720, 3750, 3780};
// region -> 5 negative region indices (region 8 = {2,4,5,6,7}; verified vs ref)
__constant__ int c_negidx[9][5] = {
    {1,3,4,2,6},
    {0,2,3,4,5},
    {0,1,4,5,8},
    {0,1,4,6,7},
    {0,1,3,5,7},
    {1,2,4,7,8},
    {0,3,4,7,8},
    {3,4,5,6,8},
    {2,4,5,6,7}
};

// Fixed-point cell accumulators [pair][region][{S,D1,D2}].
// Integer atomics: order-independent => bit-deterministic across replays.
// Zeroed by the last block each launch (static zero-init covers launch #1).
__device__ unsigned long long g_acc[NPAIR][NREG][3];
__device__ unsigned int       g_count;   // ticket; last block resets each launch

struct Patch { float a, b, c, d, ss; };

__device__ __forceinline__ Patch load_patch(const float* __restrict__ plane, int base) {
    // base always even -> 8-byte aligned float2 loads
    float2 v01 = *reinterpret_cast<const float2*>(plane + base);
    float2 v23 = *reinterpret_cast<const float2*>(plane + base + WIDTH);
    Patch p;
    p.a = v01.x; p.b = v01.y; p.c = v23.x; p.d = v23.y;
    p.ss = fmaf(p.a, p.a, fmaf(p.b, p.b, fmaf(p.c, p.c, p.d * p.d)));
    return p;
}

// exp(cos(p,q)/TEMP) with clamp cos = dot / max(na*nb, EPS); TEMP = 0.1
__device__ __forceinline__ float cexp(const Patch& p, const Patch& q) {
    float dot = fmaf(p.a, q.a, fmaf(p.b, q.b, fmaf(p.c, q.c, p.d * q.d)));
    float d2  = p.ss * q.ss;                  // (na*nb)^2
    float inv = rsqrtf(d2);
    float cosv = (d2 >= EPSV * EPSV) ? dot * inv : dot * (1.0f / EPSV);
    return __expf(cosv * 10.0f);
}

__device__ __forceinline__ unsigned long long to_fx(float v) {
    // v >= 0; (double)v * 2^28 is exact; rn-to-integer loses < 1 ulp of 2^-28.
    return __double2ull_rn((double)v * FXSCALE);
}

__global__ __launch_bounds__(NREG * 32)
void lcl_fused(const float* __restrict__ x, float* __restrict__ out) {
    const int pair  = blockIdx.y;             // 0..7
    const int chunk = blockIdx.x;             // 0..15
    const int tid   = threadIdx.x;
    const int r     = tid >> 5;               // region = warp id, 0..8
    const int lane  = tid & 31;
    const int c     = chunk * 32 + lane;      // channel 0..511

    // Stage patches in smem: [plane][region][lane]; stride 5 words -> conflict-free
    __shared__ Patch shp[2][NREG][32];
    __shared__ float shv[NCELL];
    __shared__ int   s_isLast;

    {
        const float* p1 = x + ((size_t)(2 * pair) * CHN + (size_t)c) * HW;  // batch 2k
        const float* p2 = p1 + (size_t)CHN * HW;                            // batch 2k+1
        const int pb = c_posbase[r];
        shp[0][r][lane] = load_patch(p1, pb);   // each warp loads only its region
        shp[1][r][lane] = load_patch(p2, pb);
    }
    __syncthreads();

    const Patch a1 = shp[0][r][lane];
    const Patch a2 = shp[1][r][lane];

    float S  = cexp(a1, a2);
    float D1 = 0.0f, D2 = 0.0f;

#pragma unroll
    for (int n = 0; n < 5; n++) {
        const int j = c_negidx[r][n];
        const Patch b1 = shp[0][j][lane];     // i1n patch
        const Patch b2 = shp[1][j][lane];     // i2n patch
        D1 += cexp(a1, b1) + cexp(a1, b2);
        D2 += cexp(a2, b2) + cexp(a2, b1);
    }

#pragma unroll
    for (int o = 16; o; o >>= 1) {
        S  += __shfl_xor_sync(0xffffffffu, S,  o);   // full warp active
        D1 += __shfl_xor_sync(0xffffffffu, D1, o);
        D2 += __shfl_xor_sync(0xffffffffu, D2, o);
    }
    if (lane == 0) {
        // Deterministic fixed-point accumulation (REDG at L2, no refold needed).
        atomicAdd(&g_acc[pair][r][0], to_fx(S));
        atomicAdd(&g_acc[pair][r][1], to_fx(D1));
        atomicAdd(&g_acc[pair][r][2], to_fx(D2));
        __threadfence();                      // release accumulators before ticket
    }
    __syncthreads();

    if (tid == 0)
        s_isLast = (atomicAdd(&g_count, 1u) == NBLK - 1u);
    __syncthreads();

    if (s_isLast) {
        __threadfence();                      // acquire; block-uniform, no divergence
        if (tid < NCELL) {                    // 72 cells; no sync inside this guard
            const int p  = tid / NREG;
            const int rr = tid % NREG;
            unsigned long long uS = __ldcg(&g_acc[p][rr][0]);
            unsigned long long u1 = __ldcg(&g_acc[p][rr][1]);
            unsigned long long u2 = __ldcg(&g_acc[p][rr][2]);
            float Sx = (float)((double)uS * (1.0 / FXSCALE));
            float d1 = (float)((double)u1 * (1.0 / FXSCALE));
            float d2 = (float)((double)u2 * (1.0 / FXSCALE));
            // log((S+D1)/S) + log((S+D2)/S) fused into one logf (range-safe)
            shv[tid] = logf(((Sx + d1) / Sx) * ((Sx + d2) / Sx));
            // Reset accumulators for the next graph replay (off critical path).
            g_acc[p][rr][0] = 0ull;
            g_acc[p][rr][1] = 0ull;
            g_acc[p][rr][2] = 0ull;
        }
        __syncthreads();                      // block-uniform
        if (tid == 0) {
            float tot = 0.0f;
#pragma unroll
            for (int i = 0; i < NCELL; i++) tot += shv[i];
            out[0] = tot * (1.0f / 144.0f);   // / BATCH(16) / N_REGIONS(9)
            g_count = 0;                      // reset ticket for next replay
        }
    }
}

extern "C" void kernel_launch(void* const* d_in, const int* in_sizes, int n_in,
                              void* d_out, int out_size) {
    const float* x = (const float*)d_in[0];
    float* out = (float*)d_out;
    (void)in_sizes; (void)n_in; (void)out_size;

    dim3 grid(NCHUNK, NPAIR, 1);              // 128 blocks, one wave
    dim3 block(NREG * 32, 1, 1);              // 288 threads = 9 warps (1 per region)
    lcl_fused<<<grid, block>>>(x, out);
}